// round 16
// baseline (speedup 1.0000x reference)
#include <cuda_runtime.h>
#include <cuda_bf16.h>
#include <cstdint>

typedef unsigned long long u64;

// ---------------- packed fp32 + cluster helpers (sm_103a) ----------------
__device__ __forceinline__ u64 dup2(float x) {
    u64 r; asm("mov.b64 %0, {%1, %1};" : "=l"(r) : "f"(x)); return r;
}
__device__ __forceinline__ u64 pack2(float lo, float hi) {
    u64 r; asm("mov.b64 %0, {%1, %2};" : "=l"(r) : "f"(lo), "f"(hi)); return r;
}
__device__ __forceinline__ u64 fma2(u64 a, u64 b, u64 c) {
    u64 d; asm("fma.rn.f32x2 %0, %1, %2, %3;" : "=l"(d) : "l"(a), "l"(b), "l"(c));
    return d;
}
__device__ __forceinline__ u64 add2(u64 a, u64 b) {
    u64 d; asm("add.rn.f32x2 %0, %1, %2;" : "=l"(d) : "l"(a), "l"(b));
    return d;
}
__device__ __forceinline__ void unpack2(float& lo, float& hi, u64 v) {
    asm("mov.b64 {%0, %1}, %2;" : "=f"(lo), "=f"(hi) : "l"(v));
}
__device__ __forceinline__ float fold2(u64 v) {
    float lo, hi; unpack2(lo, hi, v); return lo + hi;
}
__device__ __forceinline__ u64 shfl_bfly_u64(u64 v, int m) {
    uint32_t lo, hi;
    asm("mov.b64 {%0, %1}, %2;" : "=r"(lo), "=r"(hi) : "l"(v));
    lo = __shfl_xor_sync(0xffffffffu, lo, m);
    hi = __shfl_xor_sync(0xffffffffu, hi, m);
    u64 r; asm("mov.b64 %0, {%1, %2};" : "=l"(r) : "r"(lo), "r"(hi));
    return r;
}
__device__ __forceinline__ uint32_t smem_u32(const void* p) {
    uint32_t a;
    asm("{ .reg .u64 t0; cvta.to.shared.u64 t0, %1; cvt.u32.u64 %0, t0; }"
        : "=r"(a) : "l"(p));
    return a;
}
__device__ __forceinline__ uint32_t mapa32(uint32_t saddr, uint32_t rank) {
    uint32_t r_;
    asm("mapa.shared::cluster.u32 %0, %1, %2;" : "=r"(r_) : "r"(saddr), "r"(rank));
    return r_;
}
__device__ __forceinline__ void st_cluster_v4(uint32_t addr, float4 v) {
    asm volatile("st.shared::cluster.v4.f32 [%0], {%1,%2,%3,%4};"
                 :: "r"(addr), "f"(v.x), "f"(v.y), "f"(v.z), "f"(v.w) : "memory");
}
__device__ __forceinline__ void mbar_init(uint32_t addr, uint32_t count) {
    asm volatile("mbarrier.init.shared.b64 [%0], %1;" :: "r"(addr), "r"(count) : "memory");
}
__device__ __forceinline__ void mbar_arrive_rel(uint32_t raddr) {
    asm volatile("mbarrier.arrive.release.cluster.shared::cluster.b64 _, [%0];"
                 :: "r"(raddr) : "memory");
}
__device__ __forceinline__ void mbar_wait_acq(uint32_t mbar, uint32_t parity) {
    asm volatile(
        "{\n\t"
        ".reg .pred P;\n\t"
        "MW_%=:\n\t"
        "mbarrier.try_wait.parity.acquire.cluster.shared::cta.b64 P, [%0], %1, 0x989680;\n\t"
        "@P bra.uni MD_%=;\n\t"
        "bra.uni MW_%=;\n\t"
        "MD_%=:\n\t"
        "}"
        :: "r"(mbar), "r"(parity) : "memory");
}
__device__ __forceinline__ uint32_t ctarank() {
    uint32_t r; asm("mov.u32 %0, %%cluster_ctarank;" : "=r"(r)); return r;
}
__device__ __forceinline__ void cluster_sync_() {
    asm volatile("barrier.cluster.arrive.aligned;" ::: "memory");
    asm volatile("barrier.cluster.wait.aligned;" ::: "memory");
}
// fast tanh: clamp then (e^2s - 1)/(e^2s + 1)
__device__ __forceinline__ float tanh_fast(float s) {
    float sc = fminf(fmaxf(s, -15.0f), 15.0f);
    float e  = __expf(2.0f * sc);
    return __fdividef(e - 1.0f, e + 1.0f);
}

// =====================================================================
// Kernel 1: out = inputs @ W_xh + b_h   (M=65536, K=256, N=512)
// 128x128x8 tile; next k-tile's LDG issued before current compute.
// =====================================================================
__global__ void __launch_bounds__(256)
xw_gemm_kernel(const float* __restrict__ A, const float* __restrict__ B,
               const float* __restrict__ bias, float* __restrict__ C) {
    __shared__ __align__(16) float As[8][128];
    __shared__ __align__(16) float Bs[8][128];
    const int tid = threadIdx.x;
    const int bn  = blockIdx.x;
    const int bm  = blockIdx.y;
    const int tx  = tid & 15;
    const int ty  = tid >> 4;
    const int arow = tid >> 1, acol = (tid & 1) << 2;
    const int brow = tid >> 5, bcol = (tid & 31) << 2;
    const float* Ab = A + (size_t)bm * 128 * 256;
    const float* Bb = B + bn * 128;

    u64 acc2[8][4];
#pragma unroll
    for (int i = 0; i < 8; i++)
#pragma unroll
        for (int j = 0; j < 4; j++) acc2[i][j] = 0ull;

    float4 av = *(const float4*)(Ab + (size_t)arow * 256 + acol);
    float4 bv = *(const float4*)(Bb + (size_t)brow * 512 + bcol);

    for (int k0 = 0; k0 < 256; k0 += 8) {
        As[acol + 0][arow] = av.x;
        As[acol + 1][arow] = av.y;
        As[acol + 2][arow] = av.z;
        As[acol + 3][arow] = av.w;
        *(float4*)&Bs[brow][bcol] = bv;
        __syncthreads();
        if (k0 + 8 < 256) {
            av = *(const float4*)(Ab + (size_t)arow * 256 + (k0 + 8) + acol);
            bv = *(const float4*)(Bb + (size_t)(k0 + 8 + brow) * 512 + bcol);
        }
#pragma unroll
        for (int k = 0; k < 8; k++) {
            float4 a0 = *(const float4*)&As[k][ty * 8];
            float4 a1 = *(const float4*)&As[k][ty * 8 + 4];
            const u64* bp = (const u64*)&Bs[k][tx * 8];
            u64 b2[4];
#pragma unroll
            for (int j = 0; j < 4; j++) b2[j] = bp[j];
            u64 ad[8];
            ad[0] = dup2(a0.x); ad[1] = dup2(a0.y);
            ad[2] = dup2(a0.z); ad[3] = dup2(a0.w);
            ad[4] = dup2(a1.x); ad[5] = dup2(a1.y);
            ad[6] = dup2(a1.z); ad[7] = dup2(a1.w);
#pragma unroll
            for (int i = 0; i < 8; i++)
#pragma unroll
                for (int j = 0; j < 4; j++)
                    acc2[i][j] = fma2(ad[i], b2[j], acc2[i][j]);
        }
        __syncthreads();
    }

    float bi[8];
#pragma unroll
    for (int j = 0; j < 8; j++) bi[j] = bias[bn * 128 + tx * 8 + j];
#pragma unroll
    for (int i = 0; i < 8; i++) {
        size_t row = (size_t)bm * 128 + ty * 8 + i;
        float* cp = C + row * 512 + bn * 128 + tx * 8;
        float v[8];
#pragma unroll
        for (int j = 0; j < 4; j++) unpack2(v[2 * j], v[2 * j + 1], acc2[i][j]);
#pragma unroll
        for (int j = 0; j < 8; j++) v[j] += bi[j];
        *(float4*)(cp + 0) = make_float4(v[0], v[1], v[2], v[3]);
        *(float4*)(cp + 4) = make_float4(v[4], v[5], v[6], v[7]);
    }
}

// =====================================================================
// Kernel 2: recurrence. 32 clusters x 8 CTAs x 256 threads, 2 CTAs/SM.
// NO __syncthreads in the loop. Warp w owns cols [8w, 8w+8) over ALL
// 512 k; lane ln covers k-pairs {ln+32q}. 16 accs (8 cols x 2 batches,
// k-pair packed) reduced across lanes by a payload-halving shfl
// butterfly (xor 16,8,4,2 distribute ids; xor 1 final sum).
// Lane id after butterfly: id = (b4<<3)|(b3<<2)|(b2<<1)|b1 of ln;
// c = id>>1, b = id&1; lanes ln, ln^1 duplicate (even lane owns).
// Send: warp w's 64 B fragment (4 kpair-float4s) to all 8 ranks:
// lane -> (rank = ln>>2, frag = ln&3), 1 st.cluster.v4 + 1 release-
// arrive per lane (hoisted mapa). Consumer waits one combined
// full[buf] mbarrier, count 256 (8 CTAs x 8 warps x 4 lanes/rank).
// Overwrite safety: R10 transitive argument — every lane that read a
// buffer arrives on the barrier writers must pass before overwriting.
// =====================================================================
// float offsets in dynamic smem
#define WSM_OFF  0            // [8 warps][5 cols][256 kp] u64 = 20480 floats
#define HB_OFF   20480        // [2][256 kp][4] h = 2048 floats (8 KB)
#define STG_OFF  22528        // [2][8 warps][16] = 256 floats
#define MB_OFF   22784        // full[2] mbarriers = 4 floats
#define K2_FLOATS 22788
#define K2_SMEM_BYTES (K2_FLOATS * 4)      // 91,152 B

__global__ void __launch_bounds__(256, 2) __cluster_dims__(8, 1, 1)
rnn_rec_kernel(const float* __restrict__ W_hh, float* __restrict__ out) {
    extern __shared__ __align__(16) float smem[];
    u64*   wsm   = (u64*)(smem + WSM_OFF);
    float* hb    = smem + HB_OFF;
    float* stage = smem + STG_OFF;

    const int tid = threadIdx.x;
    const uint32_t rr = ctarank();
    const int w  = tid >> 5;            // warp: cols [8w, 8w+8)
    const int ln = tid & 31;
    const int cluster = (int)(blockIdx.x >> 3);

    // ---- W init: k-pair packed; cols 0..2 -> regs, 3..7 -> smem ----
    u64 wreg[24];
    {
#pragma unroll
        for (int q = 0; q < 8; q++) {
            int kp = ln + 32 * q;
            const float* w0 = W_hh + (size_t)(2 * kp) * 512 + rr * 64 + w * 8;
            const float* w1 = w0 + 512;
#pragma unroll
            for (int c = 0; c < 3; c++)
                wreg[q * 3 + c] = pack2(w0[c], w1[c]);
#pragma unroll
            for (int c = 3; c < 8; c++)
                wsm[(size_t)(w * 5 + (c - 3)) * 256 + kp] = pack2(w0[c], w1[c]);
        }
    }
    for (int i = tid; i < 2048; i += 256) hb[i] = 0.0f;

    const uint32_t mb_s = smem_u32(smem + MB_OFF);
    if (tid == 0) { mbar_init(mb_s, 256); mbar_init(mb_s + 8, 256); }
    __syncthreads();
    cluster_sync_();   // inits + hb zeros visible cluster-wide

    // output mapping (post-butterfly): id from lane bits 4..1
    const int id = (((ln >> 4) & 1) << 3) | (((ln >> 3) & 1) << 2) |
                   (((ln >> 2) & 1) << 1) | ((ln >> 1) & 1);
    const int c  = id >> 1;             // local col 0..7
    const int b  = id & 1;              // batch 0..1
    const int pos = (c >> 1) * 4 + b * 2 + (c & 1);  // hb k-pair format
    const bool evenlane = ((ln & 1) == 0);
    const size_t obase = ((size_t)(cluster * 2 + b) * 1024) * 512 +
                         (size_t)rr * 64 + w * 8 + c;

    const uint32_t hb_s = smem_u32(hb);
    const uint32_t rank_t = (uint32_t)(ln >> 2);
    const uint32_t remHB = mapa32(hb_s, rank_t);
    const uint32_t remF0 = mapa32(mb_s, rank_t);
    const uint32_t remF1 = mapa32(mb_s + 8, rank_t);
    const int kpg = (int)rr * 32 + w * 4 + (ln & 3);  // fragment kpair (global)

    const u64* wq = wsm + (size_t)(w * 5) * 256 + ln;

    float xw_next = out[obase];
    int ph0 = 0, ph1 = 0;

    for (int t = 0; t < 1024; t++) {
        const int j  = t & 1;
        const int jr = j ^ 1;
        const float xw_v = xw_next;
        const size_t oidx = obase + (size_t)t * 512;

        // ---- wait the combined slice barrier ----
        if (t > 0) {
            if (jr == 0) { mbar_wait_acq(mb_s, ph0);     ph0 ^= 1; }
            else         { mbar_wait_acq(mb_s + 8, ph1); ph1 ^= 1; }
        }

        // ---- GEMV: 8 cols x 2 batches, k-pairs {ln+32q} ----
        u64 acc[16];
#pragma unroll
        for (int i = 0; i < 16; i++) acc[i] = 0ull;
        const ulonglong2* hp = (const ulonglong2*)(hb + jr * 1024);
#pragma unroll
        for (int q = 0; q < 8; q++) {
            ulonglong2 hv = hp[ln + 32 * q];   // {b0 pair, b1 pair}
            u64 wv[8];
            wv[0] = wreg[q * 3 + 0];
            wv[1] = wreg[q * 3 + 1];
            wv[2] = wreg[q * 3 + 2];
            wv[3] = wq[0 * 256 + 32 * q];
            wv[4] = wq[1 * 256 + 32 * q];
            wv[5] = wq[2 * 256 + 32 * q];
            wv[6] = wq[3 * 256 + 32 * q];
            wv[7] = wq[4 * 256 + 32 * q];
#pragma unroll
            for (int cc = 0; cc < 8; cc++) {
                acc[cc * 2 + 0] = fma2(wv[cc], hv.x, acc[cc * 2 + 0]);
                acc[cc * 2 + 1] = fma2(wv[cc], hv.y, acc[cc * 2 + 1]);
            }
        }

        // ---- payload-halving butterfly across lanes ----
        {
            const bool s = (ln & 16);
#pragma unroll
            for (int i = 0; i < 8; i++) {
                u64 give = s ? acc[i] : acc[i + 8];
                u64 keep = s ? acc[i + 8] : acc[i];
                acc[i] = add2(keep, shfl_bfly_u64(give, 16));
            }
        }
        {
            const bool s = (ln & 8);
#pragma unroll
            for (int i = 0; i < 4; i++) {
                u64 give = s ? acc[i] : acc[i + 4];
                u64 keep = s ? acc[i + 4] : acc[i];
                acc[i] = add2(keep, shfl_bfly_u64(give, 8));
            }
        }
        {
            const bool s = (ln & 4);
#pragma unroll
            for (int i = 0; i < 2; i++) {
                u64 give = s ? acc[i] : acc[i + 2];
                u64 keep = s ? acc[i + 2] : acc[i];
                acc[i] = add2(keep, shfl_bfly_u64(give, 4));
            }
        }
        {
            const bool s = (ln & 2);
            u64 give = s ? acc[0] : acc[1];
            u64 keep = s ? acc[1] : acc[0];
            acc[0] = add2(keep, shfl_bfly_u64(give, 2));
        }
        acc[0] = add2(acc[0], shfl_bfly_u64(acc[0], 1));

        // ---- finalize: xw + tanh, STG, stage fragment ----
        float h = tanh_fast(fold2(acc[0]) + xw_v);
        float* stg_j = stage + j * 128;
        if (evenlane) {
            out[oidx] = h;
            stg_j[w * 16 + pos] = h;
        }
        __syncwarp();

        // ---- send warp fragment to all 8 ranks ----
        if (t < 1023) {
            float4 v = *(const float4*)(stg_j + w * 16 + (ln & 3) * 4);
            st_cluster_v4(remHB + (uint32_t)(j * 4096 + kpg * 16), v);
            mbar_arrive_rel(j == 0 ? remF0 : remF1);
            if (evenlane) xw_next = out[oidx + 512];
        }
    }
    cluster_sync_();
}

// =====================================================================
extern "C" void kernel_launch(void* const* d_in, const int* in_sizes, int n_in,
                              void* d_out, int out_size) {
    const float* inputs = (const float*)d_in[0];  // (64,1024,256)
    const float* W_xh   = (const float*)d_in[1];  // (256,512)
    const float* W_hh   = (const float*)d_in[2];  // (512,512)
    const float* b_h    = (const float*)d_in[3];  // (512,)
    float* out = (float*)d_out;                   // (64,1024,512)

    cudaFuncSetAttribute(rnn_rec_kernel,
                         cudaFuncAttributeMaxDynamicSharedMemorySize,
                         K2_SMEM_BYTES);

    dim3 g1(4, 512);
    xw_gemm_kernel<<<g1, 256>>>(inputs, W_xh, b_h, out);

    rnn_rec_kernel<<<256, 256, K2_SMEM_BYTES>>>(W_hh, out);
}

// round 17
// speedup vs baseline: 1.1223x; 1.1223x over previous
#include <cuda_runtime.h>
#include <cuda_bf16.h>
#include <cstdint>

typedef unsigned long long u64;

// ---------------- packed fp32 + cluster helpers (sm_103a) ----------------
__device__ __forceinline__ u64 dup2(float x) {
    u64 r; asm("mov.b64 %0, {%1, %1};" : "=l"(r) : "f"(x)); return r;
}
__device__ __forceinline__ u64 pack2(float lo, float hi) {
    u64 r; asm("mov.b64 %0, {%1, %2};" : "=l"(r) : "f"(lo), "f"(hi)); return r;
}
__device__ __forceinline__ u64 fma2(u64 a, u64 b, u64 c) {
    u64 d; asm("fma.rn.f32x2 %0, %1, %2, %3;" : "=l"(d) : "l"(a), "l"(b), "l"(c));
    return d;
}
__device__ __forceinline__ void unpack2(float& lo, float& hi, u64 v) {
    asm("mov.b64 {%0, %1}, %2;" : "=f"(lo), "=f"(hi) : "l"(v));
}
__device__ __forceinline__ float fold2(u64 v) {
    float lo, hi; unpack2(lo, hi, v); return lo + hi;
}
__device__ __forceinline__ uint32_t smem_u32(const void* p) {
    uint32_t a;
    asm("{ .reg .u64 t0; cvta.to.shared.u64 t0, %1; cvt.u32.u64 %0, t0; }"
        : "=r"(a) : "l"(p));
    return a;
}
__device__ __forceinline__ uint32_t mapa32(uint32_t saddr, uint32_t rank) {
    uint32_t r_;
    asm("mapa.shared::cluster.u32 %0, %1, %2;" : "=r"(r_) : "r"(saddr), "r"(rank));
    return r_;
}
__device__ __forceinline__ void st_cluster_v4(uint32_t addr, float4 v) {
    asm volatile("st.shared::cluster.v4.f32 [%0], {%1,%2,%3,%4};"
                 :: "r"(addr), "f"(v.x), "f"(v.y), "f"(v.z), "f"(v.w) : "memory");
}
__device__ __forceinline__ void mbar_init(uint32_t addr, uint32_t count) {
    asm volatile("mbarrier.init.shared.b64 [%0], %1;" :: "r"(addr), "r"(count) : "memory");
}
__device__ __forceinline__ void mbar_arrive_rel(uint32_t raddr) {
    asm volatile("mbarrier.arrive.release.cluster.shared::cluster.b64 _, [%0];"
                 :: "r"(raddr) : "memory");
}
__device__ __forceinline__ void mbar_wait_acq(uint32_t mbar, uint32_t parity) {
    asm volatile(
        "{\n\t"
        ".reg .pred P;\n\t"
        "MW_%=:\n\t"
        "mbarrier.try_wait.parity.acquire.cluster.shared::cta.b64 P, [%0], %1, 0x989680;\n\t"
        "@P bra.uni MD_%=;\n\t"
        "bra.uni MW_%=;\n\t"
        "MD_%=:\n\t"
        "}"
        :: "r"(mbar), "r"(parity) : "memory");
}
__device__ __forceinline__ uint32_t ctarank() {
    uint32_t r; asm("mov.u32 %0, %%cluster_ctarank;" : "=r"(r)); return r;
}
__device__ __forceinline__ void cluster_sync_() {
    asm volatile("barrier.cluster.arrive.aligned;" ::: "memory");
    asm volatile("barrier.cluster.wait.aligned;" ::: "memory");
}
// fast tanh: clamp then (e^2s - 1)/(e^2s + 1)
__device__ __forceinline__ float tanh_fast(float s) {
    float sc = fminf(fmaxf(s, -15.0f), 15.0f);
    float e  = __expf(2.0f * sc);
    return __fdividef(e - 1.0f, e + 1.0f);
}

// =====================================================================
// Kernel 1: out = inputs @ W_xh + b_h   (M=65536, K=256, N=512)
// 128x128x8 tile, DOUBLE-BUFFERED smem: one __syncthreads per k-tile,
// LDG (regs) overlaps compute, STS goes to the inactive buffer.
// =====================================================================
__global__ void __launch_bounds__(256)
xw_gemm_kernel(const float* __restrict__ A, const float* __restrict__ B,
               const float* __restrict__ bias, float* __restrict__ C) {
    __shared__ __align__(16) float As[2][8][128];
    __shared__ __align__(16) float Bs[2][8][128];
    const int tid = threadIdx.x;
    const int bn  = blockIdx.x;
    const int bm  = blockIdx.y;
    const int tx  = tid & 15;
    const int ty  = tid >> 4;
    const int arow = tid >> 1, acol = (tid & 1) << 2;
    const int brow = tid >> 5, bcol = (tid & 31) << 2;
    const float* Ab = A + (size_t)bm * 128 * 256;
    const float* Bb = B + bn * 128;

    u64 acc2[8][4];
#pragma unroll
    for (int i = 0; i < 8; i++)
#pragma unroll
        for (int j = 0; j < 4; j++) acc2[i][j] = 0ull;

    // preload + stage tile 0 into buffer 0
    {
        float4 av = *(const float4*)(Ab + (size_t)arow * 256 + acol);
        float4 bv = *(const float4*)(Bb + (size_t)brow * 512 + bcol);
        As[0][acol + 0][arow] = av.x;
        As[0][acol + 1][arow] = av.y;
        As[0][acol + 2][arow] = av.z;
        As[0][acol + 3][arow] = av.w;
        *(float4*)&Bs[0][brow][bcol] = bv;
    }
    __syncthreads();

    int p = 0;
    for (int k0 = 0; k0 < 256; k0 += 8) {
        float4 av, bv;
        const bool more = (k0 + 8 < 256);
        if (more) {   // issue next tile's LDG first; drains during compute
            av = *(const float4*)(Ab + (size_t)arow * 256 + (k0 + 8) + acol);
            bv = *(const float4*)(Bb + (size_t)(k0 + 8 + brow) * 512 + bcol);
        }
#pragma unroll
        for (int k = 0; k < 8; k++) {
            float4 a0 = *(const float4*)&As[p][k][ty * 8];
            float4 a1 = *(const float4*)&As[p][k][ty * 8 + 4];
            const u64* bp = (const u64*)&Bs[p][k][tx * 8];
            u64 b2[4];
#pragma unroll
            for (int j = 0; j < 4; j++) b2[j] = bp[j];
            u64 ad[8];
            ad[0] = dup2(a0.x); ad[1] = dup2(a0.y);
            ad[2] = dup2(a0.z); ad[3] = dup2(a0.w);
            ad[4] = dup2(a1.x); ad[5] = dup2(a1.y);
            ad[6] = dup2(a1.z); ad[7] = dup2(a1.w);
#pragma unroll
            for (int i = 0; i < 8; i++)
#pragma unroll
                for (int j = 0; j < 4; j++)
                    acc2[i][j] = fma2(ad[i], b2[j], acc2[i][j]);
        }
        if (more) {   // stage next tile into the inactive buffer
            const int q = p ^ 1;
            As[q][acol + 0][arow] = av.x;
            As[q][acol + 1][arow] = av.y;
            As[q][acol + 2][arow] = av.z;
            As[q][acol + 3][arow] = av.w;
            *(float4*)&Bs[q][brow][bcol] = bv;
        }
        __syncthreads();
        p ^= 1;
    }

    float bi[8];
#pragma unroll
    for (int j = 0; j < 8; j++) bi[j] = bias[bn * 128 + tx * 8 + j];
#pragma unroll
    for (int i = 0; i < 8; i++) {
        size_t row = (size_t)bm * 128 + ty * 8 + i;
        float* cp = C + row * 512 + bn * 128 + tx * 8;
        float v[8];
#pragma unroll
        for (int j = 0; j < 4; j++) unpack2(v[2 * j], v[2 * j + 1], acc2[i][j]);
#pragma unroll
        for (int j = 0; j < 8; j++) v[j] += bi[j];
        *(float4*)(cp + 0) = make_float4(v[0], v[1], v[2], v[3]);
        *(float4*)(cp + 4) = make_float4(v[4], v[5], v[6], v[7]);
    }
}

// =====================================================================
// Kernel 2: recurrence (byte-identical to R14 best, rec = 1926 us).
// 32 clusters x 8 CTAs x 256 threads, 2 CTAs/SM. k-pair f32x2 packing,
// non-duplicated h (4 KB out + 4 KB in per CTA/step), full[2][8]
// count-32 per-slice mbarriers, warp-w -> rank-w send, hoisted mapa.
// =====================================================================
// float offsets in dynamic smem
#define WSM_OFF  0            // [8][32][32] u64 = 16384 floats (64 KB)
#define HB_OFF   16384        // [2][256][4] h = 2048 floats (8 KB)
#define RED_OFF  18432        // [16][66] floats = 1056
#define STG_OFF  (RED_OFF + 1056)          // [32][4] slice = 128 floats
#define MB_OFF   (STG_OFF + 128)           // full[2][8] = 16 mbarriers
#define K2_FLOATS (MB_OFF + 32)
#define K2_SMEM_BYTES (K2_FLOATS * 4)      // 78,592 B

__global__ void __launch_bounds__(256, 2) __cluster_dims__(8, 1, 1)
rnn_rec_kernel(const float* __restrict__ W_hh, float* __restrict__ out) {
    extern __shared__ __align__(16) float smem[];
    u64*   wsm = (u64*)(smem + WSM_OFF);
    float* hb  = smem + HB_OFF;
    float* red = smem + RED_OFF;
    float* stg = smem + STG_OFF;

    const int tid = threadIdx.x;
    const uint32_t rr = ctarank();
    const int w  = tid >> 5;            // warp 0..7; k in [64w, 64w+64)
    const int ln = tid & 31;
    const int c0 = 2 * ln;              // cols c0, c0+1
    const int cluster = (int)(blockIdx.x >> 3);

    // ---- W: k-pair packed. col c0 -> regs, col c0+1 -> smem ----
    u64 wregA[32];
    {
        const float* wg = W_hh + (size_t)(64 * w) * 512 + rr * 64 + c0;
#pragma unroll
        for (int kk = 0; kk < 32; kk++) {
            float2 r0 = *(const float2*)(wg + (size_t)(2 * kk) * 512);
            float2 r1 = *(const float2*)(wg + (size_t)(2 * kk + 1) * 512);
            wregA[kk] = pack2(r0.x, r1.x);                        // col c0
            wsm[(size_t)(w * 32 + kk) * 32 + ln] = pack2(r0.y, r1.y); // col c0+1
        }
    }
    for (int i = tid; i < 2048; i += 256) hb[i] = 0.0f;

    // ---- mbarriers: full[2][8], count 32 ----
    const uint32_t mb_s = smem_u32(smem + MB_OFF);
    if (tid == 0) {
#pragma unroll
        for (int b = 0; b < 2; b++)
            for (int s = 0; s < 8; s++)
                mbar_init(mb_s + (b * 8 + s) * 8, 32);
    }
    __syncthreads();
    cluster_sync_();   // peers' inits + hb zeros visible before any remote op

    // reduce/output mapping (tid < 128): col rc, batch rb
    const int rc = tid & 63;
    const int rb = (tid >> 6) & 1;

    const uint32_t hb_s = smem_u32(hb);
    const uint32_t remHB = mapa32(hb_s, (uint32_t)w);
    const uint32_t remFA = mapa32(mb_s + (0 * 8 + (int)rr) * 8, (uint32_t)w);
    const uint32_t remFB = mapa32(mb_s + (1 * 8 + (int)rr) * 8, (uint32_t)w);
    const uint32_t fullW0 = mb_s + (0 * 8 + w) * 8;
    const uint32_t fullW1 = mb_s + (1 * 8 + w) * 8;

    const size_t obase = ((size_t)(cluster * 2 + rb) * 1024) * 512 +
                         (size_t)rr * 64 + rc;
    const float4* stg4 = (const float4*)stg;
    const u64* wqB = wsm + (size_t)(w * 32) * 32 + ln;
    const int stg_idx = (rc >> 1) * 4 + rb * 2 + (rc & 1);

    float xw_next = (tid < 128) ? out[obase] : 0.0f;

    int phF0 = 0, phF1 = 0;

    for (int t = 0; t < 1024; t++) {
        const int j  = t & 1;
        const int jr = j ^ 1;
        const float xw_v = xw_next;
        const size_t oidx = obase + (size_t)t * 512;

        // ---- wait only MY slice (from rank w) ----
        if (t > 0) {
            if (jr == 0) { mbar_wait_acq(fullW0, phF0); phF0 ^= 1; }
            else         { mbar_wait_acq(fullW1, phF1); phF1 ^= 1; }
        }

        // ---- GEMV: k-pair packed, 2 cols x 2 batches per lane ----
        u64 a00 = 0ull, a01 = 0ull, a10 = 0ull, a11 = 0ull;
        const ulonglong2* hp =
            (const ulonglong2*)(hb + (size_t)jr * 1024) + w * 32;
#pragma unroll
        for (int kk = 0; kk < 32; kk++) {
            ulonglong2 hv = hp[kk];   // hv.x={b0e,b0o}, hv.y={b1e,b1o}
            u64 wA = wregA[kk];
            u64 wB = wqB[(size_t)kk * 32];
            a00 = fma2(wA, hv.x, a00);
            a01 = fma2(wA, hv.y, a01);
            a10 = fma2(wB, hv.x, a10);
            a11 = fma2(wB, hv.y, a11);
        }
        {
            float s00 = fold2(a00), s10 = fold2(a10);
            float s01 = fold2(a01), s11 = fold2(a11);
            *(u64*)(red + (w * 2 + 0) * 66 + c0) = pack2(s00, s10);
            *(u64*)(red + (w * 2 + 1) * 66 + c0) = pack2(s01, s11);
        }
        __syncthreads();

        // ---- reduce 8 partials + xw, tanh, store, stage ----
        if (tid < 128) {
            float s = xw_v;
#pragma unroll
            for (int ww = 0; ww < 8; ww++)
                s += red[(ww * 2 + rb) * 66 + rc];
            float h = tanh_fast(s);
            out[oidx] = h;
            stg[stg_idx] = h;
        }
        __syncthreads();

        // ---- send my slice (512 B) warp w -> rank w ----
        if (t < 1023) {
            float4 v = stg4[ln];
            uint32_t dst = remHB +
                (uint32_t)(j * 4096 + ((int)rr * 32 + ln) * 16);
            st_cluster_v4(dst, v);
            mbar_arrive_rel(j == 0 ? remFA : remFB);
            if (tid < 128) xw_next = out[oidx + 512];
        }
    }
    cluster_sync_();
}

// =====================================================================
extern "C" void kernel_launch(void* const* d_in, const int* in_sizes, int n_in,
                              void* d_out, int out_size) {
    const float* inputs = (const float*)d_in[0];  // (64,1024,256)
    const float* W_xh   = (const float*)d_in[1];  // (256,512)
    const float* W_hh   = (const float*)d_in[2];  // (512,512)
    const float* b_h    = (const float*)d_in[3];  // (512,)
    float* out = (float*)d_out;                   // (64,1024,512)

    cudaFuncSetAttribute(rnn_rec_kernel,
                         cudaFuncAttributeMaxDynamicSharedMemorySize,
                         K2_SMEM_BYTES);

    dim3 g1(4, 512);
    xw_gemm_kernel<<<g1, 256>>>(inputs, W_xh, b_h, out);

    rnn_rec_kernel<<<256, 256, K2_SMEM_BYTES>>>(W_hh, out);
}